// round 13
// baseline (speedup 1.0000x reference)
#include <cuda_runtime.h>
#include <cuda_bf16.h>
#include <cuda_fp16.h>
#include <cstddef>
#include <cstdint>

#define NN   50000
#define HIDD 128
#define EK   400000
#define NK   5
#define TOT  (NK*EK)
#define GG   500
#define NLAYERS 5       // l = 0..4
#define NTILES  391     // ceil(50000/128)
#define NCONVS  15
#define CAP   64        // bucket capacity per (slice,dst); deg ~ Poisson(8)

// ---------------- static device scratch ----------------
__device__ __align__(256) __half g_xh[NLAYERS][NN*HIDD];    // activations fp16 (single)
__device__ __align__(256) __half g_hmm[NK][NN*HIDD];        // dinv-prefolded GEMM results (fp16)
__device__ __align__(256) __half g_whf[NCONVS*HIDD*HIDD];   // weights fp16 (single)
__device__ int   g_bcnt[NK][NN];
__device__ int   g_bsrc[NK][NN*CAP];
__device__ float g_pool[GG*256];    // [ssum(128) | smax-bits(128)]
__device__ int   g_cnt[GG];

// ---------------- helpers ----------------
__device__ __forceinline__ uint32_t smem_u32(const void* p) {
    uint32_t a;
    asm("{ .reg .u64 t; cvta.to.shared.u64 t, %1; cvt.u32.u64 %0, t; }" : "=r"(a) : "l"(p));
    return a;
}
__device__ __forceinline__ void ldsm4(uint32_t* r, uint32_t addr) {
    asm volatile("ldmatrix.sync.aligned.m8n8.x4.shared.b16 {%0,%1,%2,%3}, [%4];"
        : "=r"(r[0]), "=r"(r[1]), "=r"(r[2]), "=r"(r[3]) : "r"(addr));
}
__device__ __forceinline__ void mma16816h(float* c, const uint32_t* a, const uint32_t* b) {
    asm volatile("mma.sync.aligned.m16n8k16.row.col.f32.f16.f16.f32 "
        "{%0,%1,%2,%3}, {%4,%5,%6,%7}, {%8,%9}, {%0,%1,%2,%3};"
        : "+f"(c[0]), "+f"(c[1]), "+f"(c[2]), "+f"(c[3])
        : "r"(a[0]), "r"(a[1]), "r"(a[2]), "r"(a[3]), "r"(b[0]), "r"(b[1]));
}
__device__ __forceinline__ void cpasync16(uint32_t dst, const void* src, int sz) {
    asm volatile("cp.async.ca.shared.global [%0], [%1], 16, %2;"
        :: "r"(dst), "l"(src), "r"(sz) : "memory");
}
#define CP_COMMIT() asm volatile("cp.async.commit_group;" ::: "memory")
#define CP_WAIT1()  asm volatile("cp.async.wait_group 1;" ::: "memory")

__device__ __forceinline__ uint32_t pack2h(__half a, __half b) {
    return (uint32_t)__half_as_ushort(a) | ((uint32_t)__half_as_ushort(b) << 16);
}
__device__ __forceinline__ void split_h(float v, __half& h, __half& lo) {
    h  = __float2half_rn(v);
    lo = __float2half_rn(v - __half2float(h));
}

// ---------------- prep: zero counters/pool + weight fp16 convert ----------------
__global__ void prep_kernel(const float* __restrict__ conv_W) {
    int i = blockIdx.x * blockDim.x + threadIdx.x;
    if (i < NK * NN) ((int*)g_bcnt)[i] = 0;
    if (i < GG*256) g_pool[i] = 0.0f;
    if (i < GG)     g_cnt[i] = 0;
    if (i < NCONVS*HIDD*HIDD) g_whf[i] = __float2half_rn(conv_W[i]);
}

// ---------------- bucket scatter ----------------
__global__ void scatter_kernel(const int* __restrict__ ei) {
    int e = blockIdx.x * blockDim.x + threadIdx.x;
    if (e >= TOT) return;
    int k   = e / EK;
    int src = ei[e];
    int dst = ei[TOT + e];
    int pos = atomicAdd(&g_bcnt[k][dst], 1);
    if (pos < CAP) g_bsrc[k][dst * CAP + pos] = src;
}

// ---------------- HMMA embedding GEMM: x0 = x @ emb_W^T + emb_b (3-pass hi/lo) ----------------
#define ESM_TOTAL 65536

__global__ __launch_bounds__(256)
void emb_mma_kernel(const float* __restrict__ x, const float* __restrict__ emb_W,
                    const float* __restrict__ emb_b, __half* __restrict__ out) {
    extern __shared__ char smem[];
    const int tid = threadIdx.x, wid = tid >> 5, lane = tid & 31;
    const int warpM = wid >> 2, warpN = wid & 3;
    const int row0 = blockIdx.x * 128;
    uint32_t sb = smem_u32(smem);
    const uint32_t sAh = sb, sAl = sb + 16384, sWh = sb + 32768, sWl = sb + 49152;

    {
        int col = tid & 31;
        #pragma unroll
        for (int it = 0; it < 16; it++) {
            int r = it * 8 + (tid >> 5);
            uint32_t off = (uint32_t)(r * 128 + (((col >> 3) ^ (r & 7)) << 4) + (col & 7) * 2);
            int grow = row0 + r;
            float av = (grow < NN) ? x[(size_t)grow * 32 + col] : 0.0f;
            __half h, lo;
            split_h(av, h, lo);
            *(__half*)(smem + off)         = h;
            *(__half*)(smem + 16384 + off) = lo;
            float wv = emb_W[(size_t)r * 32 + col];
            split_h(wv, h, lo);
            *(__half*)(smem + 32768 + off) = h;
            *(__half*)(smem + 49152 + off) = lo;
        }
    }
    __syncthreads();

    const int lr = lane & 15, lc = lane >> 4;
    float acc[4][4][4];
    #pragma unroll
    for (int i = 0; i < 4; i++)
        #pragma unroll
        for (int j = 0; j < 4; j++)
            #pragma unroll
            for (int f = 0; f < 4; f++) acc[i][j][f] = 0.0f;

    #pragma unroll
    for (int kc = 0; kc < 2; kc++) {
        uint32_t ahf[4][4], alf[4][4], whf[4][2], wlf[4][2];
        int ch = kc * 2 + lc;
        #pragma unroll
        for (int i = 0; i < 4; i++) {
            int row = warpM * 64 + i * 16 + lr;
            uint32_t roff = row * 128 + ((ch ^ (row & 7)) << 4);
            ldsm4(ahf[i], sAh + roff);
            ldsm4(alf[i], sAl + roff);
        }
        #pragma unroll
        for (int j2 = 0; j2 < 2; j2++) {
            int row = warpN * 32 + j2 * 16 + lr;
            uint32_t roff = row * 128 + ((ch ^ (row & 7)) << 4);
            uint32_t t[4];
            ldsm4(t, sWh + roff);
            whf[j2*2+0][0] = t[0]; whf[j2*2+0][1] = t[2];
            whf[j2*2+1][0] = t[1]; whf[j2*2+1][1] = t[3];
            ldsm4(t, sWl + roff);
            wlf[j2*2+0][0] = t[0]; wlf[j2*2+0][1] = t[2];
            wlf[j2*2+1][0] = t[1]; wlf[j2*2+1][1] = t[3];
        }
        #pragma unroll
        for (int i = 0; i < 4; i++)
            #pragma unroll
            for (int j = 0; j < 4; j++) {
                mma16816h(acc[i][j], ahf[i], whf[j]);
                mma16816h(acc[i][j], alf[i], whf[j]);
                mma16816h(acc[i][j], ahf[i], wlf[j]);
            }
    }

    int rbase = row0 + warpM * 64;
    #pragma unroll
    for (int i = 0; i < 4; i++) {
        int r0 = rbase + i * 16 + (lane >> 2);
        int r8 = r0 + 8;
        #pragma unroll
        for (int j = 0; j < 4; j++) {
            int c0 = warpN * 32 + j * 8 + (lane & 3) * 2;
            float2 bv = *(const float2*)(emb_b + c0);
            if (r0 < NN)
                *(__half2*)(out + (size_t)r0 * HIDD + c0) =
                    __floats2half2_rn(acc[i][j][0] + bv.x, acc[i][j][1] + bv.y);
            if (r8 < NN)
                *(__half2*)(out + (size_t)r8 * HIDD + c0) =
                    __floats2half2_rn(acc[i][j][2] + bv.x, acc[i][j][3] + bv.y);
        }
    }
}

// ---------------- HMMA fp16 1-pass GEMM: hmm[kk] = dinv[kk] * (x[l-kk] @ W[ci]^T) ----------------
// launch_bounds(256,2): cap regs at 128 so 2 CTAs fit the 64K RF -> 16 warps/SM
#define SMEM_TOTAL (3*32768)

__device__ __forceinline__ void load_tile_async(uint32_t sbase, const __half* __restrict__ g,
                                                int row0, int maxrow) {
    int tid = threadIdx.x;
    #pragma unroll
    for (int i = 0; i < 8; i++) {
        int q = tid + i * 256;
        int r = q >> 4;
        int c = q & 15;
        uint32_t off = sbase + r * 256 + ((c ^ (r & 7)) << 4);
        int grow = row0 + r;
        int ok = (grow < maxrow);
        const void* src = g + (size_t)(ok ? grow : 0) * HIDD + c * 8;
        cpasync16(off, src, ok ? 16 : 0);
    }
}

__global__ __launch_bounds__(256, 2)
void mma_gemm_kernel(int l) {
    extern __shared__ char smem[];
    const int tid = threadIdx.x, wid = tid >> 5, lane = tid & 31;
    const int warpM = wid >> 2, warpN = wid & 3;
    const int kk = blockIdx.y;
    const int ci = l * (l + 1) / 2 + kk;
    const __half* Ax = g_xh[l - kk];
    const __half* Wf = g_whf + (size_t)ci * HIDD * HIDD;
    const int* bcnt = g_bcnt[kk];
    __half* outp = g_hmm[kk];
    uint32_t sb = smem_u32(smem);
    const uint32_t sB  = sb;
    const uint32_t sA0 = sb + 32768, sA1 = sb + 65536;

    load_tile_async(sB, Wf, 0, 1 << 30);
    int mt = blockIdx.x;
    load_tile_async(sA0, Ax, mt * 128, NN);
    CP_COMMIT();

    const int lr = lane & 15, lc = lane >> 4;
    int buf = 0;
    for (; mt < NTILES; mt += gridDim.x) {
        int nmt = mt + gridDim.x;
        uint32_t aCur = buf ? sA1 : sA0;
        uint32_t aNxt = buf ? sA0 : sA1;
        if (nmt < NTILES)
            load_tile_async(aNxt, Ax, nmt * 128, NN);
        CP_COMMIT();
        CP_WAIT1();
        __syncthreads();

        float acc[4][4][4];
        #pragma unroll
        for (int i = 0; i < 4; i++)
            #pragma unroll
            for (int j = 0; j < 4; j++)
                #pragma unroll
                for (int f = 0; f < 4; f++) acc[i][j][f] = 0.0f;

        #pragma unroll
        for (int kc = 0; kc < 8; kc++) {
            uint32_t af[4][4], bf[4][2];
            int ch = kc * 2 + lc;
            #pragma unroll
            for (int i = 0; i < 4; i++) {
                int row = warpM * 64 + i * 16 + lr;
                ldsm4(af[i], aCur + row * 256 + ((ch ^ (row & 7)) << 4));
            }
            #pragma unroll
            for (int j2 = 0; j2 < 2; j2++) {
                int row = warpN * 32 + j2 * 16 + lr;
                uint32_t t[4];
                ldsm4(t, sB + row * 256 + ((ch ^ (row & 7)) << 4));
                bf[j2*2+0][0] = t[0]; bf[j2*2+0][1] = t[2];
                bf[j2*2+1][0] = t[1]; bf[j2*2+1][1] = t[3];
            }
            #pragma unroll
            for (int i = 0; i < 4; i++)
                #pragma unroll
                for (int j = 0; j < 4; j++)
                    mma16816h(acc[i][j], af[i], bf[j]);
        }

        // epilogue: inline dinv prefold + fp16 store
        int rbase = mt * 128 + warpM * 64;
        #pragma unroll
        for (int i = 0; i < 4; i++) {
            int r0 = rbase + i * 16 + (lane >> 2);
            int r8 = r0 + 8;
            float dv0 = (r0 < NN) ? rsqrtf((float)bcnt[r0] + 1.0f) : 0.0f;
            float dv8 = (r8 < NN) ? rsqrtf((float)bcnt[r8] + 1.0f) : 0.0f;
            #pragma unroll
            for (int j = 0; j < 4; j++) {
                int c0 = warpN * 32 + j * 8 + (lane & 3) * 2;
                if (r0 < NN)
                    *(__half2*)(outp + (size_t)r0 * HIDD + c0) =
                        __floats2half2_rn(acc[i][j][0] * dv0, acc[i][j][1] * dv0);
                if (r8 < NN)
                    *(__half2*)(outp + (size_t)r8 * HIDD + c0) =
                        __floats2half2_rn(acc[i][j][2] * dv8, acc[i][j][3] * dv8);
            }
        }
        __syncthreads();
        buf ^= 1;
    }
}

// ---------------- fused aggregation (R11 version: warp per dst, uniform row gather) ------------
// out[d] = relu( Σ_kk s·dinv[kk][d]·(hmm'[d] + Σ_src hmm'[src]) + s·b )  (hmm' dinv-prefolded)
__global__ __launch_bounds__(256)
void agg_kernel(int l, const float* __restrict__ conv_b, const int* __restrict__ batch) {
    int gw   = (blockIdx.x * blockDim.x + threadIdx.x) >> 5;
    int lane = threadIdx.x & 31;
    if (gw >= NN) return;
    int d = gw;
    float4 acc = make_float4(0.f, 0.f, 0.f, 0.f);
    int base_ci = l * (l + 1) / 2;

    for (int kk = 0; kk <= l; kk++) {
        float s = 1.0f / (float)(kk + 1);
        const int cdeg = g_bcnt[kk][d];
        float dinvd = rsqrtf((float)cdeg + 1.0f);
        const __half* hmm = g_hmm[kk];

        uint2 sv = *(const uint2*)(hmm + (size_t)d * HIDD + lane * 4);
        float2 p0 = __half22float2(*(const __half2*)&sv.x);
        float2 p1 = __half22float2(*(const __half2*)&sv.y);
        float4 sum = make_float4(p0.x, p0.y, p1.x, p1.y);

        int c = min(cdeg, CAP);
        const int* bk = &g_bsrc[kk][d * CAP];
        for (int e0 = 0; e0 < c; e0 += 32) {
            int e = e0 + lane;
            int srcI = (e < c) ? bk[e] : 0;
            int m = min(32, c - e0);
            int j = 0;
            for (; j + 2 <= m; j += 2) {     // 2 independent coalesced gathers in flight
                int s0 = __shfl_sync(0xffffffffu, srcI, j);
                int s1 = __shfl_sync(0xffffffffu, srcI, j + 1);
                uint2 v0 = *(const uint2*)(hmm + (size_t)s0 * HIDD + lane * 4);
                uint2 v1 = *(const uint2*)(hmm + (size_t)s1 * HIDD + lane * 4);
                float2 a0 = __half22float2(*(const __half2*)&v0.x);
                float2 a1 = __half22float2(*(const __half2*)&v0.y);
                float2 b0 = __half22float2(*(const __half2*)&v1.x);
                float2 b1 = __half22float2(*(const __half2*)&v1.y);
                sum.x += a0.x + b0.x; sum.y += a0.y + b0.y;
                sum.z += a1.x + b1.x; sum.w += a1.y + b1.y;
            }
            if (j < m) {
                int s0 = __shfl_sync(0xffffffffu, srcI, j);
                uint2 v0 = *(const uint2*)(hmm + (size_t)s0 * HIDD + lane * 4);
                float2 a0 = __half22float2(*(const __half2*)&v0.x);
                float2 a1 = __half22float2(*(const __half2*)&v0.y);
                sum.x += a0.x; sum.y += a0.y; sum.z += a1.x; sum.w += a1.y;
            }
        }

        float4 bv = ((const float4*)(conv_b + (size_t)(base_ci + kk) * HIDD))[lane];
        float sdv = s * dinvd;
        acc.x = fmaf(sdv, sum.x, fmaf(s, bv.x, acc.x));
        acc.y = fmaf(sdv, sum.y, fmaf(s, bv.y, acc.y));
        acc.z = fmaf(sdv, sum.z, fmaf(s, bv.z, acc.z));
        acc.w = fmaf(sdv, sum.w, fmaf(s, bv.w, acc.w));
    }
    acc.x = fmaxf(acc.x, 0.f); acc.y = fmaxf(acc.y, 0.f);
    acc.z = fmaxf(acc.z, 0.f); acc.w = fmaxf(acc.w, 0.f);

    if (l == NLAYERS - 1) {
        // fused pooling (post-relu >= 0, so int-bit atomicMax == float max; pool zero-inited)
        int g = batch[d];
        float* ss = &g_pool[(size_t)g * 256];
        int*   sm = (int*)&g_pool[(size_t)g * 256 + 128];
        atomicAdd(&ss[lane*4 + 0], acc.x);
        atomicAdd(&ss[lane*4 + 1], acc.y);
        atomicAdd(&ss[lane*4 + 2], acc.z);
        atomicAdd(&ss[lane*4 + 3], acc.w);
        atomicMax(&sm[lane*4 + 0], __float_as_int(acc.x));
        atomicMax(&sm[lane*4 + 1], __float_as_int(acc.y));
        atomicMax(&sm[lane*4 + 2], __float_as_int(acc.z));
        atomicMax(&sm[lane*4 + 3], __float_as_int(acc.w));
        if (lane == 0) atomicAdd(&g_cnt[g], 1);
    } else {
        uint2 ph;
        ph.x = pack2h(__float2half_rn(acc.x), __float2half_rn(acc.y));
        ph.y = pack2h(__float2half_rn(acc.z), __float2half_rn(acc.w));
        *(uint2*)(g_xh[l + 1] + (size_t)d * HIDD + lane * 4) = ph;
    }
}

// ---------------- readout: [ssum|smax|smean] @ r1^T -> leaky -> @ r2^T ----------------
__global__ __launch_bounds__(384)
void readout_kernel(const float* __restrict__ r1W, const float* __restrict__ r1b,
                    const float* __restrict__ r2W, const float* __restrict__ r2b,
                    float* __restrict__ out) {
    int g = blockIdx.x, tid = threadIdx.x;
    __shared__ float sp[384];
    __shared__ float sh[192];
    if (tid < 256) sp[tid] = g_pool[(size_t)g * 256 + tid];
    __syncthreads();
    if (tid < 128) {
        float c = fmaxf((float)g_cnt[g], 1.0f);
        sp[256 + tid] = sp[tid] / c;       // smean
    }
    __syncthreads();
    if (tid < 192) {
        float a = r1b[tid];
        const float4* w = (const float4*)&r1W[(size_t)tid * 384];
        #pragma unroll 8
        for (int j = 0; j < 96; j++) {
            float4 wv = w[j];
            float4 pv = *(const float4*)&sp[j*4];
            a = fmaf(wv.x, pv.x, a); a = fmaf(wv.y, pv.y, a);
            a = fmaf(wv.z, pv.z, a); a = fmaf(wv.w, pv.w, a);
        }
        sh[tid] = (a >= 0.0f) ? a : 0.01f * a;
    }
    __syncthreads();
    if (tid < 10) {
        float a = r2b[tid];
        const float4* w = (const float4*)&r2W[(size_t)tid * 192];
        #pragma unroll
        for (int j = 0; j < 48; j++) {
            float4 wv = w[j];
            float4 pv = *(const float4*)&sh[j*4];
            a = fmaf(wv.x, pv.x, a); a = fmaf(wv.y, pv.y, a);
            a = fmaf(wv.z, pv.z, a); a = fmaf(wv.w, pv.w, a);
        }
        out[g * 10 + tid] = a;
    }
}

// ---------------- launch ----------------
extern "C" void kernel_launch(void* const* d_in, const int* in_sizes, int n_in,
                              void* d_out, int out_size) {
    const float* x      = (const float*)d_in[0];
    const int*   ei     = (const int*)d_in[1];
    const int*   batch  = (const int*)d_in[3];
    const float* emb_W  = (const float*)d_in[4];
    const float* emb_b  = (const float*)d_in[5];
    const float* conv_W = (const float*)d_in[6];
    const float* conv_b = (const float*)d_in[7];
    const float* r1_W   = (const float*)d_in[8];
    const float* r1_b   = (const float*)d_in[9];
    const float* r2_W   = (const float*)d_in[10];
    const float* r2_b   = (const float*)d_in[11];
    float* out = (float*)d_out;

    cudaFuncSetAttribute(mma_gemm_kernel, cudaFuncAttributeMaxDynamicSharedMemorySize, SMEM_TOTAL);
    cudaFuncSetAttribute(emb_mma_kernel, cudaFuncAttributeMaxDynamicSharedMemorySize, ESM_TOTAL);

    __half* x0;
    {
        void* p;
        cudaGetSymbolAddress(&p, g_xh); x0 = (__half*)p;
    }

    // 1. prep: zero bucket counters/pool + fp16 weight convert
    prep_kernel<<<(NK * NN + 255) / 256, 256>>>(conv_W);
    // 2. bucket scatter (dinv computed inline from counts downstream)
    scatter_kernel<<<(TOT + 255) / 256, 256>>>(ei);
    // 3. embedding via HMMA (3-pass hi/lo, near-exact) -> fp16 x0
    emb_mma_kernel<<<NTILES, 256, ESM_TOTAL>>>(x, emb_W, emb_b, x0);

    // 4. layers: HMMA fp16 1-pass batched GEMMs + fused aggregation (last fuses pooling)
    //    grids sized for ~296 total CTAs per launch -> 2 resident CTAs/SM (regs capped at 128)
    static const int gx[NLAYERS] = {296, 148, 99, 74, 59};
    for (int l = 0; l < NLAYERS; l++) {
        dim3 grid(gx[l], l + 1);
        mma_gemm_kernel<<<grid, 256, SMEM_TOTAL>>>(l);
        agg_kernel<<<(NN * 32 + 255) / 256, 256>>>(l, conv_b, batch);
    }

    // 5. readout (smean folded in)
    readout_kernel<<<GG, 384>>>(r1_W, r1_b, r2_W, r2_b, out);
}

// round 14
// speedup vs baseline: 1.2817x; 1.2817x over previous
#include <cuda_runtime.h>
#include <cuda_bf16.h>
#include <cuda_fp16.h>
#include <cstddef>
#include <cstdint>

#define NN   50000
#define HIDD 128
#define EK   400000
#define NK   5
#define TOT  (NK*EK)
#define GG   500
#define NLAYERS 5       // l = 0..4
#define NTILES  391     // ceil(50000/128)
#define NCONVS  15
#define CAP   64        // bucket capacity per (slice,dst); deg ~ Poisson(8)

// ---------------- static device scratch ----------------
__device__ __align__(256) __half g_xh[NLAYERS][NN*HIDD];    // activations fp16 (single)
__device__ __align__(256) __half g_hmm[NK][NN*HIDD];        // dinv-prefolded GEMM results (fp16)
__device__ __align__(256) __half g_whf[NCONVS*HIDD*HIDD];   // weights fp16 (single)
__device__ int   g_bcnt[NK][NN];
__device__ int   g_bsrc[NK][NN*CAP];
__device__ float g_pool[GG*256];    // [ssum(128) | smax-bits(128)]
__device__ int   g_cnt[GG];

// ---------------- helpers ----------------
__device__ __forceinline__ uint32_t smem_u32(const void* p) {
    uint32_t a;
    asm("{ .reg .u64 t; cvta.to.shared.u64 t, %1; cvt.u32.u64 %0, t; }" : "=r"(a) : "l"(p));
    return a;
}
__device__ __forceinline__ void ldsm4(uint32_t* r, uint32_t addr) {
    asm volatile("ldmatrix.sync.aligned.m8n8.x4.shared.b16 {%0,%1,%2,%3}, [%4];"
        : "=r"(r[0]), "=r"(r[1]), "=r"(r[2]), "=r"(r[3]) : "r"(addr));
}
__device__ __forceinline__ void mma16816h(float* c, const uint32_t* a, const uint32_t* b) {
    asm volatile("mma.sync.aligned.m16n8k16.row.col.f32.f16.f16.f32 "
        "{%0,%1,%2,%3}, {%4,%5,%6,%7}, {%8,%9}, {%0,%1,%2,%3};"
        : "+f"(c[0]), "+f"(c[1]), "+f"(c[2]), "+f"(c[3])
        : "r"(a[0]), "r"(a[1]), "r"(a[2]), "r"(a[3]), "r"(b[0]), "r"(b[1]));
}
__device__ __forceinline__ void cpasync16(uint32_t dst, const void* src, int sz) {
    asm volatile("cp.async.ca.shared.global [%0], [%1], 16, %2;"
        :: "r"(dst), "l"(src), "r"(sz) : "memory");
}
#define CP_COMMIT() asm volatile("cp.async.commit_group;" ::: "memory")
#define CP_WAIT2()  asm volatile("cp.async.wait_group 2;" ::: "memory")

__device__ __forceinline__ uint32_t pack2h(__half a, __half b) {
    return (uint32_t)__half_as_ushort(a) | ((uint32_t)__half_as_ushort(b) << 16);
}
__device__ __forceinline__ void split_h(float v, __half& h, __half& lo) {
    h  = __float2half_rn(v);
    lo = __float2half_rn(v - __half2float(h));
}

// ---------------- prep: zero counters/pool + weight fp16 convert ----------------
__global__ void prep_kernel(const float* __restrict__ conv_W) {
    int i = blockIdx.x * blockDim.x + threadIdx.x;
    if (i < NK * NN) ((int*)g_bcnt)[i] = 0;
    if (i < GG*256) g_pool[i] = 0.0f;
    if (i < GG)     g_cnt[i] = 0;
    if (i < NCONVS*HIDD*HIDD) g_whf[i] = __float2half_rn(conv_W[i]);
}

// ---------------- bucket scatter ----------------
__global__ void scatter_kernel(const int* __restrict__ ei) {
    int e = blockIdx.x * blockDim.x + threadIdx.x;
    if (e >= TOT) return;
    int k   = e / EK;
    int src = ei[e];
    int dst = ei[TOT + e];
    int pos = atomicAdd(&g_bcnt[k][dst], 1);
    if (pos < CAP) g_bsrc[k][dst * CAP + pos] = src;
}

// ---------------- HMMA embedding GEMM: x0 = x @ emb_W^T + emb_b (3-pass hi/lo) ----------------
#define ESM_TOTAL 65536

__global__ __launch_bounds__(256)
void emb_mma_kernel(const float* __restrict__ x, const float* __restrict__ emb_W,
                    const float* __restrict__ emb_b, __half* __restrict__ out) {
    extern __shared__ char smem[];
    const int tid = threadIdx.x, wid = tid >> 5, lane = tid & 31;
    const int warpM = wid >> 2, warpN = wid & 3;
    const int row0 = blockIdx.x * 128;
    uint32_t sb = smem_u32(smem);
    const uint32_t sAh = sb, sAl = sb + 16384, sWh = sb + 32768, sWl = sb + 49152;

    {
        int col = tid & 31;
        #pragma unroll
        for (int it = 0; it < 16; it++) {
            int r = it * 8 + (tid >> 5);
            uint32_t off = (uint32_t)(r * 128 + (((col >> 3) ^ (r & 7)) << 4) + (col & 7) * 2);
            int grow = row0 + r;
            float av = (grow < NN) ? x[(size_t)grow * 32 + col] : 0.0f;
            __half h, lo;
            split_h(av, h, lo);
            *(__half*)(smem + off)         = h;
            *(__half*)(smem + 16384 + off) = lo;
            float wv = emb_W[(size_t)r * 32 + col];
            split_h(wv, h, lo);
            *(__half*)(smem + 32768 + off) = h;
            *(__half*)(smem + 49152 + off) = lo;
        }
    }
    __syncthreads();

    const int lr = lane & 15, lc = lane >> 4;
    float acc[4][4][4];
    #pragma unroll
    for (int i = 0; i < 4; i++)
        #pragma unroll
        for (int j = 0; j < 4; j++)
            #pragma unroll
            for (int f = 0; f < 4; f++) acc[i][j][f] = 0.0f;

    #pragma unroll
    for (int kc = 0; kc < 2; kc++) {
        uint32_t ahf[4][4], alf[4][4], whf[4][2], wlf[4][2];
        int ch = kc * 2 + lc;
        #pragma unroll
        for (int i = 0; i < 4; i++) {
            int row = warpM * 64 + i * 16 + lr;
            uint32_t roff = row * 128 + ((ch ^ (row & 7)) << 4);
            ldsm4(ahf[i], sAh + roff);
            ldsm4(alf[i], sAl + roff);
        }
        #pragma unroll
        for (int j2 = 0; j2 < 2; j2++) {
            int row = warpN * 32 + j2 * 16 + lr;
            uint32_t roff = row * 128 + ((ch ^ (row & 7)) << 4);
            uint32_t t[4];
            ldsm4(t, sWh + roff);
            whf[j2*2+0][0] = t[0]; whf[j2*2+0][1] = t[2];
            whf[j2*2+1][0] = t[1]; whf[j2*2+1][1] = t[3];
            ldsm4(t, sWl + roff);
            wlf[j2*2+0][0] = t[0]; wlf[j2*2+0][1] = t[2];
            wlf[j2*2+1][0] = t[1]; wlf[j2*2+1][1] = t[3];
        }
        #pragma unroll
        for (int i = 0; i < 4; i++)
            #pragma unroll
            for (int j = 0; j < 4; j++) {
                mma16816h(acc[i][j], ahf[i], whf[j]);
                mma16816h(acc[i][j], alf[i], whf[j]);
                mma16816h(acc[i][j], ahf[i], wlf[j]);
            }
    }

    int rbase = row0 + warpM * 64;
    #pragma unroll
    for (int i = 0; i < 4; i++) {
        int r0 = rbase + i * 16 + (lane >> 2);
        int r8 = r0 + 8;
        #pragma unroll
        for (int j = 0; j < 4; j++) {
            int c0 = warpN * 32 + j * 8 + (lane & 3) * 2;
            float2 bv = *(const float2*)(emb_b + c0);
            if (r0 < NN)
                *(__half2*)(out + (size_t)r0 * HIDD + c0) =
                    __floats2half2_rn(acc[i][j][0] + bv.x, acc[i][j][1] + bv.y);
            if (r8 < NN)
                *(__half2*)(out + (size_t)r8 * HIDD + c0) =
                    __floats2half2_rn(acc[i][j][2] + bv.x, acc[i][j][3] + bv.y);
        }
    }
}

// ---------------- HMMA fp16 1-pass GEMM: hmm[kk] = dinv[kk] * (x[l-kk] @ W[ci]^T) ----------------
// 3-stage A pipeline: B @0, A buffers @32K/64K/96K. wait_group 2 keeps 2 tile-loads in flight.
#define SMEM_TOTAL (4*32768)

__device__ __forceinline__ void load_tile_async(uint32_t sbase, const __half* __restrict__ g,
                                                int row0, int maxrow) {
    int tid = threadIdx.x;
    #pragma unroll
    for (int i = 0; i < 8; i++) {
        int q = tid + i * 256;
        int r = q >> 4;
        int c = q & 15;
        uint32_t off = sbase + r * 256 + ((c ^ (r & 7)) << 4);
        int grow = row0 + r;
        int ok = (grow < maxrow);
        const void* src = g + (size_t)(ok ? grow : 0) * HIDD + c * 8;
        cpasync16(off, src, ok ? 16 : 0);
    }
}

__global__ __launch_bounds__(256)
void mma_gemm_kernel(int l) {
    extern __shared__ char smem[];
    const int tid = threadIdx.x, wid = tid >> 5, lane = tid & 31;
    const int warpM = wid >> 2, warpN = wid & 3;
    const int kk = blockIdx.y;
    const int ci = l * (l + 1) / 2 + kk;
    const __half* Ax = g_xh[l - kk];
    const __half* Wf = g_whf + (size_t)ci * HIDD * HIDD;
    const int* bcnt = g_bcnt[kk];
    __half* outp = g_hmm[kk];
    uint32_t sb = smem_u32(smem);
    const uint32_t sB = sb;
    const uint32_t sA[3] = { sb + 32768, sb + 65536, sb + 98304 };
    const int stride = gridDim.x;

    // prologue: G0 = {B, A tile0}, G1 = {A tile1}
    load_tile_async(sB, Wf, 0, 1 << 30);
    int mt0 = blockIdx.x;
    load_tile_async(sA[0], Ax, mt0 * 128, NN);
    CP_COMMIT();
    if (mt0 + stride < NTILES)
        load_tile_async(sA[1], Ax, (mt0 + stride) * 128, NN);
    CP_COMMIT();

    const int lr = lane & 15, lc = lane >> 4;
    int it = 0;
    for (int mt = mt0; mt < NTILES; mt += stride, it++) {
        __syncthreads();                       // all warps done reading buf[(it+2)%3] (iter it-1)
        int pmt = mt + 2 * stride;
        if (pmt < NTILES)
            load_tile_async(sA[(it + 2) % 3], Ax, pmt * 128, NN);
        CP_COMMIT();                           // G_{it+2}
        CP_WAIT2();                            // G_it complete -> tile it resident
        __syncthreads();                       // make all threads' async writes visible

        uint32_t aCur = sA[it % 3];

        float acc[4][4][4];
        #pragma unroll
        for (int i = 0; i < 4; i++)
            #pragma unroll
            for (int j = 0; j < 4; j++)
                #pragma unroll
                for (int f = 0; f < 4; f++) acc[i][j][f] = 0.0f;

        #pragma unroll
        for (int kc = 0; kc < 8; kc++) {
            uint32_t af[4][4], bf[4][2];
            int ch = kc * 2 + lc;
            #pragma unroll
            for (int i = 0; i < 4; i++) {
                int row = warpM * 64 + i * 16 + lr;
                ldsm4(af[i], aCur + row * 256 + ((ch ^ (row & 7)) << 4));
            }
            #pragma unroll
            for (int j2 = 0; j2 < 2; j2++) {
                int row = warpN * 32 + j2 * 16 + lr;
                uint32_t t[4];
                ldsm4(t, sB + row * 256 + ((ch ^ (row & 7)) << 4));
                bf[j2*2+0][0] = t[0]; bf[j2*2+0][1] = t[2];
                bf[j2*2+1][0] = t[1]; bf[j2*2+1][1] = t[3];
            }
            #pragma unroll
            for (int i = 0; i < 4; i++)
                #pragma unroll
                for (int j = 0; j < 4; j++)
                    mma16816h(acc[i][j], af[i], bf[j]);
        }

        // epilogue: inline dinv prefold + fp16 store
        int rbase = mt * 128 + warpM * 64;
        #pragma unroll
        for (int i = 0; i < 4; i++) {
            int r0 = rbase + i * 16 + (lane >> 2);
            int r8 = r0 + 8;
            float dv0 = (r0 < NN) ? rsqrtf((float)bcnt[r0] + 1.0f) : 0.0f;
            float dv8 = (r8 < NN) ? rsqrtf((float)bcnt[r8] + 1.0f) : 0.0f;
            #pragma unroll
            for (int j = 0; j < 4; j++) {
                int c0 = warpN * 32 + j * 8 + (lane & 3) * 2;
                if (r0 < NN)
                    *(__half2*)(outp + (size_t)r0 * HIDD + c0) =
                        __floats2half2_rn(acc[i][j][0] * dv0, acc[i][j][1] * dv0);
                if (r8 < NN)
                    *(__half2*)(outp + (size_t)r8 * HIDD + c0) =
                        __floats2half2_rn(acc[i][j][2] * dv8, acc[i][j][3] * dv8);
            }
        }
    }
}

// ---------------- fused aggregation (R11 layout, unroll 4: warp per dst, uniform row gather) ----
// out[d] = relu( Σ_kk s·dinv[kk][d]·(hmm'[d] + Σ_src hmm'[src]) + s·b )  (hmm' dinv-prefolded)
__global__ __launch_bounds__(256)
void agg_kernel(int l, const float* __restrict__ conv_b, const int* __restrict__ batch) {
    int gw   = (blockIdx.x * blockDim.x + threadIdx.x) >> 5;
    int lane = threadIdx.x & 31;
    if (gw >= NN) return;
    int d = gw;
    float4 acc = make_float4(0.f, 0.f, 0.f, 0.f);
    int base_ci = l * (l + 1) / 2;

    for (int kk = 0; kk <= l; kk++) {
        float s = 1.0f / (float)(kk + 1);
        const int cdeg = g_bcnt[kk][d];
        float dinvd = rsqrtf((float)cdeg + 1.0f);
        const __half* hmm = g_hmm[kk];

        uint2 sv = *(const uint2*)(hmm + (size_t)d * HIDD + lane * 4);
        float2 p0 = __half22float2(*(const __half2*)&sv.x);
        float2 p1 = __half22float2(*(const __half2*)&sv.y);
        float4 sum = make_float4(p0.x, p0.y, p1.x, p1.y);

        int c = min(cdeg, CAP);
        const int* bk = &g_bsrc[kk][d * CAP];
        for (int e0 = 0; e0 < c; e0 += 32) {
            int e = e0 + lane;
            int srcI = (e < c) ? bk[e] : 0;
            int m = min(32, c - e0);
            int j = 0;
            for (; j + 4 <= m; j += 4) {     // 4 independent coalesced gathers in flight
                int s0 = __shfl_sync(0xffffffffu, srcI, j);
                int s1 = __shfl_sync(0xffffffffu, srcI, j + 1);
                int s2 = __shfl_sync(0xffffffffu, srcI, j + 2);
                int s3 = __shfl_sync(0xffffffffu, srcI, j + 3);
                uint2 v0 = *(const uint2*)(hmm + (size_t)s0 * HIDD + lane * 4);
                uint2 v1 = *(const uint2*)(hmm + (size_t)s1 * HIDD + lane * 4);
                uint2 v2 = *(const uint2*)(hmm + (size_t)s2 * HIDD + lane * 4);
                uint2 v3 = *(const uint2*)(hmm + (size_t)s3 * HIDD + lane * 4);
                float2 a0 = __half22float2(*(const __half2*)&v0.x);
                float2 a1 = __half22float2(*(const __half2*)&v0.y);
                float2 b0 = __half22float2(*(const __half2*)&v1.x);
                float2 b1 = __half22float2(*(const __half2*)&v1.y);
                float2 c0 = __half22float2(*(const __half2*)&v2.x);
                float2 c1 = __half22float2(*(const __half2*)&v2.y);
                float2 d0 = __half22float2(*(const __half2*)&v3.x);
                float2 d1 = __half22float2(*(const __half2*)&v3.y);
                sum.x += (a0.x + b0.x) + (c0.x + d0.x);
                sum.y += (a0.y + b0.y) + (c0.y + d0.y);
                sum.z += (a1.x + b1.x) + (c1.x + d1.x);
                sum.w += (a1.y + b1.y) + (c1.y + d1.y);
            }
            for (; j < m; j++) {
                int s0 = __shfl_sync(0xffffffffu, srcI, j);
                uint2 v0 = *(const uint2*)(hmm + (size_t)s0 * HIDD + lane * 4);
                float2 a0 = __half22float2(*(const __half2*)&v0.x);
                float2 a1 = __half22float2(*(const __half2*)&v0.y);
                sum.x += a0.x; sum.y += a0.y; sum.z += a1.x; sum.w += a1.y;
            }
        }

        float4 bv = ((const float4*)(conv_b + (size_t)(base_ci + kk) * HIDD))[lane];
        float sdv = s * dinvd;
        acc.x = fmaf(sdv, sum.x, fmaf(s, bv.x, acc.x));
        acc.y = fmaf(sdv, sum.y, fmaf(s, bv.y, acc.y));
        acc.z = fmaf(sdv, sum.z, fmaf(s, bv.z, acc.z));
        acc.w = fmaf(sdv, sum.w, fmaf(s, bv.w, acc.w));
    }
    acc.x = fmaxf(acc.x, 0.f); acc.y = fmaxf(acc.y, 0.f);
    acc.z = fmaxf(acc.z, 0.f); acc.w = fmaxf(acc.w, 0.f);

    if (l == NLAYERS - 1) {
        // fused pooling (post-relu >= 0, so int-bit atomicMax == float max; pool zero-inited)
        int g = batch[d];
        float* ss = &g_pool[(size_t)g * 256];
        int*   sm = (int*)&g_pool[(size_t)g * 256 + 128];
        atomicAdd(&ss[lane*4 + 0], acc.x);
        atomicAdd(&ss[lane*4 + 1], acc.y);
        atomicAdd(&ss[lane*4 + 2], acc.z);
        atomicAdd(&ss[lane*4 + 3], acc.w);
        atomicMax(&sm[lane*4 + 0], __float_as_int(acc.x));
        atomicMax(&sm[lane*4 + 1], __float_as_int(acc.y));
        atomicMax(&sm[lane*4 + 2], __float_as_int(acc.z));
        atomicMax(&sm[lane*4 + 3], __float_as_int(acc.w));
        if (lane == 0) atomicAdd(&g_cnt[g], 1);
    } else {
        uint2 ph;
        ph.x = pack2h(__float2half_rn(acc.x), __float2half_rn(acc.y));
        ph.y = pack2h(__float2half_rn(acc.z), __float2half_rn(acc.w));
        *(uint2*)(g_xh[l + 1] + (size_t)d * HIDD + lane * 4) = ph;
    }
}

// ---------------- readout: [ssum|smax|smean] @ r1^T -> leaky -> @ r2^T ----------------
__global__ __launch_bounds__(384)
void readout_kernel(const float* __restrict__ r1W, const float* __restrict__ r1b,
                    const float* __restrict__ r2W, const float* __restrict__ r2b,
                    float* __restrict__ out) {
    int g = blockIdx.x, tid = threadIdx.x;
    __shared__ float sp[384];
    __shared__ float sh[192];
    if (tid < 256) sp[tid] = g_pool[(size_t)g * 256 + tid];
    __syncthreads();
    if (tid < 128) {
        float c = fmaxf((float)g_cnt[g], 1.0f);
        sp[256 + tid] = sp[tid] / c;       // smean
    }
    __syncthreads();
    if (tid < 192) {
        float a = r1b[tid];
        const float4* w = (const float4*)&r1W[(size_t)tid * 384];
        #pragma unroll 8
        for (int j = 0; j < 96; j++) {
            float4 wv = w[j];
            float4 pv = *(const float4*)&sp[j*4];
            a = fmaf(wv.x, pv.x, a); a = fmaf(wv.y, pv.y, a);
            a = fmaf(wv.z, pv.z, a); a = fmaf(wv.w, pv.w, a);
        }
        sh[tid] = (a >= 0.0f) ? a : 0.01f * a;
    }
    __syncthreads();
    if (tid < 10) {
        float a = r2b[tid];
        const float4* w = (const float4*)&r2W[(size_t)tid * 192];
        #pragma unroll
        for (int j = 0; j < 48; j++) {
            float4 wv = w[j];
            float4 pv = *(const float4*)&sh[j*4];
            a = fmaf(wv.x, pv.x, a); a = fmaf(wv.y, pv.y, a);
            a = fmaf(wv.z, pv.z, a); a = fmaf(wv.w, pv.w, a);
        }
        out[g * 10 + tid] = a;
    }
}

// ---------------- launch ----------------
extern "C" void kernel_launch(void* const* d_in, const int* in_sizes, int n_in,
                              void* d_out, int out_size) {
    const float* x      = (const float*)d_in[0];
    const int*   ei     = (const int*)d_in[1];
    const int*   batch  = (const int*)d_in[3];
    const float* emb_W  = (const float*)d_in[4];
    const float* emb_b  = (const float*)d_in[5];
    const float* conv_W = (const float*)d_in[6];
    const float* conv_b = (const float*)d_in[7];
    const float* r1_W   = (const float*)d_in[8];
    const float* r1_b   = (const float*)d_in[9];
    const float* r2_W   = (const float*)d_in[10];
    const float* r2_b   = (const float*)d_in[11];
    float* out = (float*)d_out;

    cudaFuncSetAttribute(mma_gemm_kernel, cudaFuncAttributeMaxDynamicSharedMemorySize, SMEM_TOTAL);
    cudaFuncSetAttribute(emb_mma_kernel, cudaFuncAttributeMaxDynamicSharedMemorySize, ESM_TOTAL);

    __half* x0;
    {
        void* p;
        cudaGetSymbolAddress(&p, g_xh); x0 = (__half*)p;
    }

    // 1. prep: zero bucket counters/pool + fp16 weight convert
    prep_kernel<<<(NK * NN + 255) / 256, 256>>>(conv_W);
    // 2. bucket scatter (dinv computed inline from counts downstream)
    scatter_kernel<<<(TOT + 255) / 256, 256>>>(ei);
    // 3. embedding via HMMA (3-pass hi/lo, near-exact) -> fp16 x0
    emb_mma_kernel<<<NTILES, 256, ESM_TOTAL>>>(x, emb_W, emb_b, x0);

    // 4. layers: HMMA fp16 1-pass batched GEMMs (3-stage pipeline) + fused aggregation
    //    R11 grids: small CTA counts so each CTA amortizes its B-load over many tiles
    static const int gx[NLAYERS] = {131, 66, 49, 36, 28};
    for (int l = 0; l < NLAYERS; l++) {
        dim3 grid(gx[l], l + 1);
        mma_gemm_kernel<<<grid, 256, SMEM_TOTAL>>>(l);
        agg_kernel<<<(NN * 32 + 255) / 256, 256>>>(l, conv_b, batch);
    }

    // 5. readout (smean folded in)
    readout_kernel<<<GG, 384>>>(r1_W, r1_b, r2_W, r2_b, out);
}

// round 16
// speedup vs baseline: 1.3644x; 1.0645x over previous
#include <cuda_runtime.h>
#include <cuda_bf16.h>
#include <cuda_fp16.h>
#include <cstddef>
#include <cstdint>

#define NN   50000
#define HIDD 128
#define EK   400000
#define NK   5
#define TOT  (NK*EK)
#define GG   500
#define NLAYERS 5       // l = 0..4
#define NTILES  391     // ceil(50000/128)  (emb kernel, 128-row tiles)
#define TM      256     // conv GEMM tile rows
#define NT256   196     // ceil(50000/256)
#define NCONVS  15
#define CAP   64        // bucket capacity per (slice,dst); deg ~ Poisson(8)

// ---------------- static device scratch ----------------
__device__ __align__(256) __half g_xh[NLAYERS][NN*HIDD];    // activations fp16 (single)
__device__ __align__(256) __half g_hmm[NK][NN*HIDD];        // dinv-prefolded GEMM results (fp16)
__device__ __align__(256) __half g_whf[NCONVS*HIDD*HIDD];   // weights fp16 (single)
__device__ int   g_bcnt[NK][NN];
__device__ int   g_bsrc[NK][NN*CAP];
__device__ float g_pool[GG*256];    // [ssum(128) | smax-bits(128)]
__device__ int   g_cnt[GG];

// ---------------- helpers ----------------
__device__ __forceinline__ uint32_t smem_u32(const void* p) {
    uint32_t a;
    asm("{ .reg .u64 t; cvta.to.shared.u64 t, %1; cvt.u32.u64 %0, t; }" : "=r"(a) : "l"(p));
    return a;
}
__device__ __forceinline__ void ldsm4(uint32_t* r, uint32_t addr) {
    asm volatile("ldmatrix.sync.aligned.m8n8.x4.shared.b16 {%0,%1,%2,%3}, [%4];"
        : "=r"(r[0]), "=r"(r[1]), "=r"(r[2]), "=r"(r[3]) : "r"(addr));
}
__device__ __forceinline__ void mma16816h(float* c, const uint32_t* a, const uint32_t* b) {
    asm volatile("mma.sync.aligned.m16n8k16.row.col.f32.f16.f16.f32 "
        "{%0,%1,%2,%3}, {%4,%5,%6,%7}, {%8,%9}, {%0,%1,%2,%3};"
        : "+f"(c[0]), "+f"(c[1]), "+f"(c[2]), "+f"(c[3])
        : "r"(a[0]), "r"(a[1]), "r"(a[2]), "r"(a[3]), "r"(b[0]), "r"(b[1]));
}
__device__ __forceinline__ void cpasync16(uint32_t dst, const void* src, int sz) {
    asm volatile("cp.async.ca.shared.global [%0], [%1], 16, %2;"
        :: "r"(dst), "l"(src), "r"(sz) : "memory");
}
#define CP_COMMIT() asm volatile("cp.async.commit_group;" ::: "memory")
#define CP_WAIT1()  asm volatile("cp.async.wait_group 1;" ::: "memory")

__device__ __forceinline__ uint32_t pack2h(__half a, __half b) {
    return (uint32_t)__half_as_ushort(a) | ((uint32_t)__half_as_ushort(b) << 16);
}
__device__ __forceinline__ void split_h(float v, __half& h, __half& lo) {
    h  = __float2half_rn(v);
    lo = __float2half_rn(v - __half2float(h));
}

// ---------------- prep: zero counters/pool + weight fp16 convert ----------------
__global__ void prep_kernel(const float* __restrict__ conv_W) {
    int i = blockIdx.x * blockDim.x + threadIdx.x;
    if (i < NK * NN) ((int*)g_bcnt)[i] = 0;
    if (i < GG*256) g_pool[i] = 0.0f;
    if (i < GG)     g_cnt[i] = 0;
    if (i < NCONVS*HIDD*HIDD) g_whf[i] = __float2half_rn(conv_W[i]);
}

// ---------------- bucket scatter ----------------
__global__ void scatter_kernel(const int* __restrict__ ei) {
    int e = blockIdx.x * blockDim.x + threadIdx.x;
    if (e >= TOT) return;
    int k   = e / EK;
    int src = ei[e];
    int dst = ei[TOT + e];
    int pos = atomicAdd(&g_bcnt[k][dst], 1);
    if (pos < CAP) g_bsrc[k][dst * CAP + pos] = src;
}

// ---------------- HMMA embedding GEMM: x0 = x @ emb_W^T + emb_b (3-pass hi/lo) ----------------
#define ESM_TOTAL 65536

__global__ __launch_bounds__(256)
void emb_mma_kernel(const float* __restrict__ x, const float* __restrict__ emb_W,
                    const float* __restrict__ emb_b, __half* __restrict__ out) {
    extern __shared__ char smem[];
    const int tid = threadIdx.x, wid = tid >> 5, lane = tid & 31;
    const int warpM = wid >> 2, warpN = wid & 3;
    const int row0 = blockIdx.x * 128;
    uint32_t sb = smem_u32(smem);
    const uint32_t sAh = sb, sAl = sb + 16384, sWh = sb + 32768, sWl = sb + 49152;

    {
        int col = tid & 31;
        #pragma unroll
        for (int it = 0; it < 16; it++) {
            int r = it * 8 + (tid >> 5);
            uint32_t off = (uint32_t)(r * 128 + (((col >> 3) ^ (r & 7)) << 4) + (col & 7) * 2);
            int grow = row0 + r;
            float av = (grow < NN) ? x[(size_t)grow * 32 + col] : 0.0f;
            __half h, lo;
            split_h(av, h, lo);
            *(__half*)(smem + off)         = h;
            *(__half*)(smem + 16384 + off) = lo;
            float wv = emb_W[(size_t)r * 32 + col];
            split_h(wv, h, lo);
            *(__half*)(smem + 32768 + off) = h;
            *(__half*)(smem + 49152 + off) = lo;
        }
    }
    __syncthreads();

    const int lr = lane & 15, lc = lane >> 4;
    float acc[4][4][4];
    #pragma unroll
    for (int i = 0; i < 4; i++)
        #pragma unroll
        for (int j = 0; j < 4; j++)
            #pragma unroll
            for (int f = 0; f < 4; f++) acc[i][j][f] = 0.0f;

    #pragma unroll
    for (int kc = 0; kc < 2; kc++) {
        uint32_t ahf[4][4], alf[4][4], whf[4][2], wlf[4][2];
        int ch = kc * 2 + lc;
        #pragma unroll
        for (int i = 0; i < 4; i++) {
            int row = warpM * 64 + i * 16 + lr;
            uint32_t roff = row * 128 + ((ch ^ (row & 7)) << 4);
            ldsm4(ahf[i], sAh + roff);
            ldsm4(alf[i], sAl + roff);
        }
        #pragma unroll
        for (int j2 = 0; j2 < 2; j2++) {
            int row = warpN * 32 + j2 * 16 + lr;
            uint32_t roff = row * 128 + ((ch ^ (row & 7)) << 4);
            uint32_t t[4];
            ldsm4(t, sWh + roff);
            whf[j2*2+0][0] = t[0]; whf[j2*2+0][1] = t[2];
            whf[j2*2+1][0] = t[1]; whf[j2*2+1][1] = t[3];
            ldsm4(t, sWl + roff);
            wlf[j2*2+0][0] = t[0]; wlf[j2*2+0][1] = t[2];
            wlf[j2*2+1][0] = t[1]; wlf[j2*2+1][1] = t[3];
        }
        #pragma unroll
        for (int i = 0; i < 4; i++)
            #pragma unroll
            for (int j = 0; j < 4; j++) {
                mma16816h(acc[i][j], ahf[i], whf[j]);
                mma16816h(acc[i][j], alf[i], whf[j]);
                mma16816h(acc[i][j], ahf[i], wlf[j]);
            }
    }

    int rbase = row0 + warpM * 64;
    #pragma unroll
    for (int i = 0; i < 4; i++) {
        int r0 = rbase + i * 16 + (lane >> 2);
        int r8 = r0 + 8;
        #pragma unroll
        for (int j = 0; j < 4; j++) {
            int c0 = warpN * 32 + j * 8 + (lane & 3) * 2;
            float2 bv = *(const float2*)(emb_b + c0);
            if (r0 < NN)
                *(__half2*)(out + (size_t)r0 * HIDD + c0) =
                    __floats2half2_rn(acc[i][j][0] + bv.x, acc[i][j][1] + bv.y);
            if (r8 < NN)
                *(__half2*)(out + (size_t)r8 * HIDD + c0) =
                    __floats2half2_rn(acc[i][j][2] + bv.x, acc[i][j][3] + bv.y);
        }
    }
}

// ---------------- HMMA fp16 1-pass GEMM: hmm[kk] = dinv[kk] * (x[l-kk] @ W[ci]^T) ----------------
// 512 threads, 256-row tiles: 16 warps/SM for latency hiding, 1 CTA/SM (SMEM 160KB).
// SMEM: B @0 (32KB), A0 @32768 (64KB), A1 @98304 (64KB). 2-stage A pipeline (R11 schedule).
#define SMEM_TOTAL (32768 + 2*65536)

__device__ __forceinline__ void load_B_async(uint32_t sbase, const __half* __restrict__ g) {
    int tid = threadIdx.x;
    #pragma unroll
    for (int i = 0; i < 4; i++) {
        int q = tid + i * 512;          // 2048 16B chunks (128 rows)
        int r = q >> 4;
        int c = q & 15;
        cpasync16(sbase + r * 256 + ((c ^ (r & 7)) << 4),
                  g + (size_t)r * HIDD + c * 8, 16);
    }
}
__device__ __forceinline__ void load_A_async(uint32_t sbase, const __half* __restrict__ g,
                                             int row0) {
    int tid = threadIdx.x;
    #pragma unroll
    for (int i = 0; i < 8; i++) {
        int q = tid + i * 512;          // 4096 16B chunks (256 rows)
        int r = q >> 4;
        int c = q & 15;
        int grow = row0 + r;
        int ok = (grow < NN);
        cpasync16(sbase + r * 256 + ((c ^ (r & 7)) << 4),
                  g + (size_t)(ok ? grow : 0) * HIDD + c * 8, ok ? 16 : 0);
    }
}

__global__ __launch_bounds__(512)
void mma_gemm_kernel(int l) {
    extern __shared__ char smem[];
    const int tid = threadIdx.x, wid = tid >> 5, lane = tid & 31;
    const int warpM = wid >> 2, warpN = wid & 3;   // warpM 0..3 (64-row slices), warpN 0..3
    const int kk = blockIdx.y;
    const int ci = l * (l + 1) / 2 + kk;
    const __half* Ax = g_xh[l - kk];
    const __half* Wf = g_whf + (size_t)ci * HIDD * HIDD;
    const int* bcnt = g_bcnt[kk];
    __half* outp = g_hmm[kk];
    uint32_t sb = smem_u32(smem);
    const uint32_t sB  = sb;
    const uint32_t sA0 = sb + 32768, sA1 = sb + 98304;

    load_B_async(sB, Wf);
    int mt = blockIdx.x;
    load_A_async(sA0, Ax, mt * TM);
    CP_COMMIT();

    const int lr = lane & 15, lc = lane >> 4;
    int buf = 0;
    for (; mt < NT256; mt += gridDim.x) {
        int nmt = mt + gridDim.x;
        uint32_t aCur = buf ? sA1 : sA0;
        uint32_t aNxt = buf ? sA0 : sA1;
        if (nmt < NT256)
            load_A_async(aNxt, Ax, nmt * TM);
        CP_COMMIT();
        CP_WAIT1();
        __syncthreads();

        float acc[4][4][4];
        #pragma unroll
        for (int i = 0; i < 4; i++)
            #pragma unroll
            for (int j = 0; j < 4; j++)
                #pragma unroll
                for (int f = 0; f < 4; f++) acc[i][j][f] = 0.0f;

        #pragma unroll
        for (int kc = 0; kc < 8; kc++) {
            uint32_t af[4][4], bf[4][2];
            int ch = kc * 2 + lc;
            #pragma unroll
            for (int i = 0; i < 4; i++) {
                int row = warpM * 64 + i * 16 + lr;          // 0..255 within A tile
                ldsm4(af[i], aCur + row * 256 + ((ch ^ (row & 7)) << 4));
            }
            #pragma unroll
            for (int j2 = 0; j2 < 2; j2++) {
                int row = warpN * 32 + j2 * 16 + lr;         // 0..127 within B tile
                uint32_t t[4];
                ldsm4(t, sB + row * 256 + ((ch ^ (row & 7)) << 4));
                bf[j2*2+0][0] = t[0]; bf[j2*2+0][1] = t[2];
                bf[j2*2+1][0] = t[1]; bf[j2*2+1][1] = t[3];
            }
            #pragma unroll
            for (int i = 0; i < 4; i++)
                #pragma unroll
                for (int j = 0; j < 4; j++)
                    mma16816h(acc[i][j], af[i], bf[j]);
        }

        // epilogue: inline dinv prefold + fp16 store
        int rbase = mt * TM + warpM * 64;
        #pragma unroll
        for (int i = 0; i < 4; i++) {
            int r0 = rbase + i * 16 + (lane >> 2);
            int r8 = r0 + 8;
            float dv0 = (r0 < NN) ? rsqrtf((float)bcnt[r0] + 1.0f) : 0.0f;
            float dv8 = (r8 < NN) ? rsqrtf((float)bcnt[r8] + 1.0f) : 0.0f;
            #pragma unroll
            for (int j = 0; j < 4; j++) {
                int c0 = warpN * 32 + j * 8 + (lane & 3) * 2;
                if (r0 < NN)
                    *(__half2*)(outp + (size_t)r0 * HIDD + c0) =
                        __floats2half2_rn(acc[i][j][0] * dv0, acc[i][j][1] * dv0);
                if (r8 < NN)
                    *(__half2*)(outp + (size_t)r8 * HIDD + c0) =
                        __floats2half2_rn(acc[i][j][2] * dv8, acc[i][j][3] * dv8);
            }
        }
        __syncthreads();
        buf ^= 1;
    }
}

// ---------------- fused aggregation (R11: warp per dst, uniform row gather, unroll 2) ----------
// out[d] = relu( Σ_kk s·dinv[kk][d]·(hmm'[d] + Σ_src hmm'[src]) + s·b )  (hmm' dinv-prefolded)
__global__ __launch_bounds__(256)
void agg_kernel(int l, const float* __restrict__ conv_b, const int* __restrict__ batch) {
    int gw   = (blockIdx.x * blockDim.x + threadIdx.x) >> 5;
    int lane = threadIdx.x & 31;
    if (gw >= NN) return;
    int d = gw;
    float4 acc = make_float4(0.f, 0.f, 0.f, 0.f);
    int base_ci = l * (l + 1) / 2;

    for (int kk = 0; kk <= l; kk++) {
        float s = 1.0f / (float)(kk + 1);
        const int cdeg = g_bcnt[kk][d];
        float dinvd = rsqrtf((float)cdeg + 1.0f);
        const __half* hmm = g_hmm[kk];

        uint2 sv = *(const uint2*)(hmm + (size_t)d * HIDD + lane * 4);
        float2 p0 = __half22float2(*(const __half2*)&sv.x);
        float2 p1 = __half22float2(*(const __half2*)&sv.y);
        float4 sum = make_float4(p0.x, p0.y, p1.x, p1.y);

        int c = min(cdeg, CAP);
        const int* bk = &g_bsrc[kk][d * CAP];
        for (int e0 = 0; e0 < c; e0 += 32) {
            int e = e0 + lane;
            int srcI = (e < c) ? bk[e] : 0;
            int m = min(32, c - e0);
            int j = 0;
            for (; j + 2 <= m; j += 2) {     // 2 independent coalesced gathers in flight
                int s0 = __shfl_sync(0xffffffffu, srcI, j);
                int s1 = __shfl_sync(0xffffffffu, srcI, j + 1);
                uint2 v0 = *(const uint2*)(hmm + (size_t)s0 * HIDD + lane * 4);
                uint2 v1 = *(const uint2*)(hmm + (size_t)s1 * HIDD + lane * 4);
                float2 a0 = __half22float2(*(const __half2*)&v0.x);
                float2 a1 = __half22float2(*(const __half2*)&v0.y);
                float2 b0 = __half22float2(*(const __half2*)&v1.x);
                float2 b1 = __half22float2(*(const __half2*)&v1.y);
                sum.x += a0.x + b0.x; sum.y += a0.y + b0.y;
                sum.z += a1.x + b1.x; sum.w += a1.y + b1.y;
            }
            if (j < m) {
                int s0 = __shfl_sync(0xffffffffu, srcI, j);
                uint2 v0 = *(const uint2*)(hmm + (size_t)s0 * HIDD + lane * 4);
                float2 a0 = __half22float2(*(const __half2*)&v0.x);
                float2 a1 = __half22float2(*(const __half2*)&v0.y);
                sum.x += a0.x; sum.y += a0.y; sum.z += a1.x; sum.w += a1.y;
            }
        }

        float4 bv = ((const float4*)(conv_b + (size_t)(base_ci + kk) * HIDD))[lane];
        float sdv = s * dinvd;
        acc.x = fmaf(sdv, sum.x, fmaf(s, bv.x, acc.x));
        acc.y = fmaf(sdv, sum.y, fmaf(s, bv.y, acc.y));
        acc.z = fmaf(sdv, sum.z, fmaf(s, bv.z, acc.z));
        acc.w = fmaf(sdv, sum.w, fmaf(s, bv.w, acc.w));
    }
    acc.x = fmaxf(acc.x, 0.f); acc.y = fmaxf(acc.y, 0.f);
    acc.z = fmaxf(acc.z, 0.f); acc.w = fmaxf(acc.w, 0.f);

    if (l == NLAYERS - 1) {
        // fused pooling (post-relu >= 0, so int-bit atomicMax == float max; pool zero-inited)
        int g = batch[d];
        float* ss = &g_pool[(size_t)g * 256];
        int*   sm = (int*)&g_pool[(size_t)g * 256 + 128];
        atomicAdd(&ss[lane*4 + 0], acc.x);
        atomicAdd(&ss[lane*4 + 1], acc.y);
        atomicAdd(&ss[lane*4 + 2], acc.z);
        atomicAdd(&ss[lane*4 + 3], acc.w);
        atomicMax(&sm[lane*4 + 0], __float_as_int(acc.x));
        atomicMax(&sm[lane*4 + 1], __float_as_int(acc.y));
        atomicMax(&sm[lane*4 + 2], __float_as_int(acc.z));
        atomicMax(&sm[lane*4 + 3], __float_as_int(acc.w));
        if (lane == 0) atomicAdd(&g_cnt[g], 1);
    } else {
        uint2 ph;
        ph.x = pack2h(__float2half_rn(acc.x), __float2half_rn(acc.y));
        ph.y = pack2h(__float2half_rn(acc.z), __float2half_rn(acc.w));
        *(uint2*)(g_xh[l + 1] + (size_t)d * HIDD + lane * 4) = ph;
    }
}

// ---------------- readout: [ssum|smax|smean] @ r1^T -> leaky -> @ r2^T ----------------
__global__ __launch_bounds__(384)
void readout_kernel(const float* __restrict__ r1W, const float* __restrict__ r1b,
                    const float* __restrict__ r2W, const float* __restrict__ r2b,
                    float* __restrict__ out) {
    int g = blockIdx.x, tid = threadIdx.x;
    __shared__ float sp[384];
    __shared__ float sh[192];
    if (tid < 256) sp[tid] = g_pool[(size_t)g * 256 + tid];
    __syncthreads();
    if (tid < 128) {
        float c = fmaxf((float)g_cnt[g], 1.0f);
        sp[256 + tid] = sp[tid] / c;       // smean
    }
    __syncthreads();
    if (tid < 192) {
        float a = r1b[tid];
        const float4* w = (const float4*)&r1W[(size_t)tid * 384];
        #pragma unroll 8
        for (int j = 0; j < 96; j++) {
            float4 wv = w[j];
            float4 pv = *(const float4*)&sp[j*4];
            a = fmaf(wv.x, pv.x, a); a = fmaf(wv.y, pv.y, a);
            a = fmaf(wv.z, pv.z, a); a = fmaf(wv.w, pv.w, a);
        }
        sh[tid] = (a >= 0.0f) ? a : 0.01f * a;
    }
    __syncthreads();
    if (tid < 10) {
        float a = r2b[tid];
        const float4* w = (const float4*)&r2W[(size_t)tid * 192];
        #pragma unroll
        for (int j = 0; j < 48; j++) {
            float4 wv = w[j];
            float4 pv = *(const float4*)&sh[j*4];
            a = fmaf(wv.x, pv.x, a); a = fmaf(wv.y, pv.y, a);
            a = fmaf(wv.z, pv.z, a); a = fmaf(wv.w, pv.w, a);
        }
        out[g * 10 + tid] = a;
    }
}

// ---------------- launch ----------------
extern "C" void kernel_launch(void* const* d_in, const int* in_sizes, int n_in,
                              void* d_out, int out_size) {
    const float* x      = (const float*)d_in[0];
    const int*   ei     = (const int*)d_in[1];
    const int*   batch  = (const int*)d_in[3];
    const float* emb_W  = (const float*)d_in[4];
    const float* emb_b  = (const float*)d_in[5];
    const float* conv_W = (const float*)d_in[6];
    const float* conv_b = (const float*)d_in[7];
    const float* r1_W   = (const float*)d_in[8];
    const float* r1_b   = (const float*)d_in[9];
    const float* r2_W   = (const float*)d_in[10];
    const float* r2_b   = (const float*)d_in[11];
    float* out = (float*)d_out;

    cudaFuncSetAttribute(mma_gemm_kernel, cudaFuncAttributeMaxDynamicSharedMemorySize, SMEM_TOTAL);
    cudaFuncSetAttribute(emb_mma_kernel, cudaFuncAttributeMaxDynamicSharedMemorySize, ESM_TOTAL);

    __half* x0;
    {
        void* p;
        cudaGetSymbolAddress(&p, g_xh); x0 = (__half*)p;
    }

    // 1. prep: zero bucket counters/pool + fp16 weight convert
    prep_kernel<<<(NK * NN + 255) / 256, 256>>>(conv_W);
    // 2. bucket scatter (dinv computed inline from counts downstream)
    scatter_kernel<<<(TOT + 255) / 256, 256>>>(ei);
    // 3. embedding via HMMA (3-pass hi/lo, near-exact) -> fp16 x0
    emb_mma_kernel<<<NTILES, 256, ESM_TOTAL>>>(x, emb_W, emb_b, x0);

    // 4. layers: HMMA fp16 1-pass GEMMs (512-thr CTAs, 256-row tiles, 16 warps/SM)
    //    + fused aggregation (last layer fuses pooling)
    //    grids: exact tile division of NT256=196 -> {2,3,4,7,7} tiles/CTA
    static const int gx[NLAYERS] = {98, 66, 49, 28, 28};
    for (int l = 0; l < NLAYERS; l++) {
        dim3 grid(gx[l], l + 1);
        mma_gemm_kernel<<<grid, 512, SMEM_TOTAL>>>(l);
        agg_kernel<<<(NN * 32 + 255) / 256, 256>>>(l, conv_b, batch);
    }

    // 5. readout (smean folded in)
    readout_kernel<<<GG, 384>>>(r1_W, r1_b, r2_W, r2_b, out);
}